// round 7
// baseline (speedup 1.0000x reference)
#include <cuda_runtime.h>
#include <cuda_bf16.h>

// loss_i = (label_i == label[N-1]) ? d2 : max(0, MARGIN - d2),  d2 = ||p_{N-1} - p_i||^2, D=3
// Output: scalar sum. Single launch, last-warp-done pattern, allocation-free,
// graph-capturable (globals reset by the finishing warp each replay).

#define MARGIN 500.0f
#define TPB 128
#define PTS_PER_THREAD 4

__device__ float        g_accum = 0.0f;
__device__ unsigned int g_count = 0u;

__global__ __launch_bounds__(TPB)
void contrastive_last_anchor_kernel(const int* __restrict__ labels,
                                    const float* __restrict__ coords,
                                    float* __restrict__ out,
                                    int n, unsigned int total_warps)
{
    const int t    = blockIdx.x * TPB + threadIdx.x;
    const int base = t * PTS_PER_THREAD;

    // ---- Issue all wide loads up front (independent -> batched, MLP=4) ----
    int4   lab = make_int4(0, 0, 0, 0);
    float4 c0 = make_float4(0.f, 0.f, 0.f, 0.f);
    float4 c1 = c0, c2 = c0;
    const bool full = (base + PTS_PER_THREAD <= n);
    if (full) {
        lab = *reinterpret_cast<const int4*>(labels + base);          // 16B aligned
        const float4* cp = reinterpret_cast<const float4*>(coords + 3 * base); // 48B -> 16B aligned
        c0 = cp[0]; c1 = cp[1]; c2 = cp[2];
    }

    // Anchor (same cache lines chip-wide -> broadcast); overlaps with the above.
    const int   al = __ldg(labels + (n - 1));
    const float ax = __ldg(coords + 3 * (n - 1) + 0);
    const float ay = __ldg(coords + 3 * (n - 1) + 1);
    const float az = __ldg(coords + 3 * (n - 1) + 2);

    float v = 0.0f;
    if (full) {
        // p0=(c0.x,c0.y,c0.z) p1=(c0.w,c1.x,c1.y) p2=(c1.z,c1.w,c2.x) p3=(c2.y,c2.z,c2.w)
        {
            const float dx = ax - c0.x, dy = ay - c0.y, dz = az - c0.z;
            const float d2 = fmaf(dx, dx, fmaf(dy, dy, dz * dz));
            v += (lab.x == al) ? d2 : fmaxf(0.0f, MARGIN - d2);
        }
        {
            const float dx = ax - c0.w, dy = ay - c1.x, dz = az - c1.y;
            const float d2 = fmaf(dx, dx, fmaf(dy, dy, dz * dz));
            v += (lab.y == al) ? d2 : fmaxf(0.0f, MARGIN - d2);
        }
        {
            const float dx = ax - c1.z, dy = ay - c1.w, dz = az - c2.x;
            const float d2 = fmaf(dx, dx, fmaf(dy, dy, dz * dz));
            v += (lab.z == al) ? d2 : fmaxf(0.0f, MARGIN - d2);
        }
        {
            const float dx = ax - c2.y, dy = ay - c2.z, dz = az - c2.w;
            const float d2 = fmaf(dx, dx, fmaf(dy, dy, dz * dz));
            v += (lab.w == al) ? d2 : fmaxf(0.0f, MARGIN - d2);
        }
    } else {
        // Generic tail (not hit for n = 32768)
        for (int i = base; i < n && i < base + PTS_PER_THREAD; i++) {
            const float dx = ax - coords[3 * i + 0];
            const float dy = ay - coords[3 * i + 1];
            const float dz = az - coords[3 * i + 2];
            const float d2 = fmaf(dx, dx, fmaf(dy, dy, dz * dz));
            v += (labels[i] == al) ? d2 : fmaxf(0.0f, MARGIN - d2);
        }
    }

    // ---- Warp reduce, then straight to global atomics (no smem, no bar) ----
    #pragma unroll
    for (int o = 16; o > 0; o >>= 1)
        v += __shfl_down_sync(0xFFFFFFFFu, v, o);

    if ((threadIdx.x & 31) == 0) {
        atomicAdd(&g_accum, v);
        __threadfence();
        const unsigned old = atomicAdd(&g_count, 1u);
        if (old == total_warps - 1u) {
            // All warps' accum atomics are fenced before their count arrives.
            const float total = atomicAdd(&g_accum, 0.0f);
            out[0] = total;
            // Reset for the next graph replay.
            atomicExch(&g_accum, 0.0f);
            atomicExch(&g_count, 0u);
            __threadfence();
        }
    }
}

extern "C" void kernel_launch(void* const* d_in, const int* in_sizes, int n_in,
                              void* d_out, int out_size)
{
    const int*   labels = (const int*)d_in[0];
    const float* coords = (const float*)d_in[1];
    float*       out    = (float*)d_out;
    const int n = in_sizes[0];

    const int pts_per_cta = TPB * PTS_PER_THREAD;                 // 512
    const int blocks = (n + pts_per_cta - 1) / pts_per_cta;       // 64 for n=32768
    const unsigned total_warps = (unsigned)blocks * (TPB / 32);   // 256

    contrastive_last_anchor_kernel<<<blocks, TPB>>>(labels, coords, out, n, total_warps);
}